// round 5
// baseline (speedup 1.0000x reference)
#include <cuda_runtime.h>
#include <math.h>

// ---------------- Problem constants ----------------
#define B_SZ   8
#define L_SEQ  2048
#define DM     1024
#define DI     2048
#define DS     16
#define DTR    64
#define MROWS  (B_SZ * L_SEQ)       // 16384
#define XDBL_W 96                   // DT_RANK + 2*D_STATE

// ---------------- Scratch (static device globals; no runtime alloc) ----------------
__device__ float g_h   [MROWS * DM];            // LN output + pos
__device__ float g_xz  [MROWS * 2 * DI];        // in_proj output (x | z)
__device__ float g_xact[2][MROWS * DI];         // conv+silu per branch (scan-time order)
__device__ float g_xdbl[2][MROWS * XDBL_W];     // x_proj output per branch
__device__ float g_dt  [2][MROWS * DI];         // dt raw (pre-bias/softplus)
__device__ float g_y   [2][MROWS * DI];         // scan output (stored at ORIGINAL l)

// ---------------- f32x2 packed-FMA helpers (sm_103a FFMA2 path) ----------------
__device__ __forceinline__ unsigned long long pk2(float lo, float hi) {
    unsigned long long r;
    asm("mov.b64 %0, {%1, %2};" : "=l"(r) : "f"(lo), "f"(hi));
    return r;
}
__device__ __forceinline__ void upk2(unsigned long long v, float& lo, float& hi) {
    asm("mov.b64 {%0, %1}, %2;" : "=f"(lo), "=f"(hi) : "l"(v));
}
__device__ __forceinline__ void ffma2(unsigned long long& d, unsigned long long a, unsigned long long b) {
    asm("fma.rn.f32x2 %0, %1, %2, %0;" : "+l"(d) : "l"(a), "l"(b));
}

// ---------------- Fused add + LayerNorm + pos-emb; also emits residual output ----------------
__global__ __launch_bounds__(256) void prenorm_kernel(
    const float* __restrict__ hs, const float* __restrict__ res,
    const float* __restrict__ pos, const float* __restrict__ w,
    const float* __restrict__ bn, float* __restrict__ resout,
    float* __restrict__ hout)
{
    const int row = blockIdx.x;
    const int tid = threadIdx.x;
    const size_t base = (size_t)row * DM;

    float v[4];
    float s = 0.f, ss = 0.f;
#pragma unroll
    for (int i = 0; i < 4; i++) {
        const int c = tid + i * 256;
        const float t = hs[base + c] + res[base + c];
        v[i] = t; s += t; ss += t * t;
    }
#pragma unroll
    for (int off = 16; off; off >>= 1) {
        s  += __shfl_xor_sync(0xffffffffu, s,  off);
        ss += __shfl_xor_sync(0xffffffffu, ss, off);
    }
    __shared__ float sw[2][8];
    const int wid = tid >> 5, lane = tid & 31;
    if (lane == 0) { sw[0][wid] = s; sw[1][wid] = ss; }
    __syncthreads();
    s = 0.f; ss = 0.f;
#pragma unroll
    for (int k = 0; k < 8; k++) { s += sw[0][k]; ss += sw[1][k]; }
    const float mu   = s * (1.f / DM);
    const float var  = ss * (1.f / DM) - mu * mu;
    const float rstd = rsqrtf(var + 1e-5f);
#pragma unroll
    for (int i = 0; i < 4; i++) {
        const int c = tid + i * 256;
        resout[base + c] = v[i];
        hout[base + c] = (v[i] - mu) * rstd * w[c] + bn[c] + pos[base + c];
    }
}

// ---------------- Generic NT SGEMM: C[M,N] = (A (+A2)) [M,K] * W[N,K]^T ----------------
// 128x128 block tile, 8x8 per thread, BK=16, f32x2 packed FMAs.
__global__ __launch_bounds__(256) void sgemm_nt(
    const float* __restrict__ A, const float* __restrict__ A2, int lda,
    const float* __restrict__ W, int ldb,
    float* __restrict__ C, int ldc, int M, int N, int K)
{
    __shared__ float As[16][128];
    __shared__ float Bs[16][128];
    const int tid = threadIdx.x;
    const int mt = blockIdx.y * 128;
    const int nt = blockIdx.x * 128;
    const int lr = tid >> 1;            // 0..127 (tile row loaded by this thread)
    const int lc = (tid & 1) * 8;       // 0 or 8  (k sub-offset)
    const int ty = tid >> 4;            // 0..15
    const int tx = tid & 15;            // 0..15

    const float* Ap  = A + (size_t)(mt + lr) * lda + lc;
    const float* A2p = A2 ? (A2 + (size_t)(mt + lr) * lda + lc) : nullptr;
    const bool   wv  = (nt + lr) < N;
    const float* Wp  = W + (size_t)(nt + lr) * ldb + lc;

    unsigned long long acc[8][4];
#pragma unroll
    for (int i = 0; i < 8; i++)
#pragma unroll
        for (int j = 0; j < 4; j++) acc[i][j] = 0ULL;

    for (int k0 = 0; k0 < K; k0 += 16) {
        float4 a0 = *(const float4*)(Ap + k0);
        float4 a1 = *(const float4*)(Ap + k0 + 4);
        if (A2p) {
            float4 c0 = *(const float4*)(A2p + k0);
            float4 c1 = *(const float4*)(A2p + k0 + 4);
            a0.x += c0.x; a0.y += c0.y; a0.z += c0.z; a0.w += c0.w;
            a1.x += c1.x; a1.y += c1.y; a1.z += c1.z; a1.w += c1.w;
        }
        float4 w0 = make_float4(0.f, 0.f, 0.f, 0.f);
        float4 w1 = make_float4(0.f, 0.f, 0.f, 0.f);
        if (wv) {
            w0 = *(const float4*)(Wp + k0);
            w1 = *(const float4*)(Wp + k0 + 4);
        }
        __syncthreads();
        As[lc + 0][lr] = a0.x; As[lc + 1][lr] = a0.y; As[lc + 2][lr] = a0.z; As[lc + 3][lr] = a0.w;
        As[lc + 4][lr] = a1.x; As[lc + 5][lr] = a1.y; As[lc + 6][lr] = a1.z; As[lc + 7][lr] = a1.w;
        Bs[lc + 0][lr] = w0.x; Bs[lc + 1][lr] = w0.y; Bs[lc + 2][lr] = w0.z; Bs[lc + 3][lr] = w0.w;
        Bs[lc + 4][lr] = w1.x; Bs[lc + 5][lr] = w1.y; Bs[lc + 6][lr] = w1.z; Bs[lc + 7][lr] = w1.w;
        __syncthreads();
#pragma unroll
        for (int kk = 0; kk < 16; kk++) {
            const float4 ra0 = *(const float4*)&As[kk][ty * 8];
            const float4 ra1 = *(const float4*)&As[kk][ty * 8 + 4];
            const float4 rb0 = *(const float4*)&Bs[kk][tx * 8];
            const float4 rb1 = *(const float4*)&Bs[kk][tx * 8 + 4];
            unsigned long long b2[4] = {
                pk2(rb0.x, rb0.y), pk2(rb0.z, rb0.w),
                pk2(rb1.x, rb1.y), pk2(rb1.z, rb1.w)
            };
            const float ra[8] = {ra0.x, ra0.y, ra0.z, ra0.w, ra1.x, ra1.y, ra1.z, ra1.w};
#pragma unroll
            for (int i = 0; i < 8; i++) {
                const unsigned long long a2 = pk2(ra[i], ra[i]);
#pragma unroll
                for (int j = 0; j < 4; j++) ffma2(acc[i][j], a2, b2[j]);
            }
        }
    }

#pragma unroll
    for (int i = 0; i < 8; i++) {
        const int m = mt + ty * 8 + i;
        if (m >= M) continue;
#pragma unroll
        for (int j = 0; j < 4; j++) {
            float lo, hi;
            upk2(acc[i][j], lo, hi);
            const int n = nt + tx * 8 + j * 2;
            if (n < N)     C[(size_t)m * ldc + n]     = lo;
            if (n + 1 < N) C[(size_t)m * ldc + n + 1] = hi;
        }
    }
}

// ---------------- Causal depthwise conv (D_CONV=4) + SiLU, both branches ----------------
// Backward branch reads x at flipped positions and stores in scan-time order.
__global__ __launch_bounds__(256) void conv_silu_kernel(
    const float* __restrict__ xz,
    const float* __restrict__ wf, const float* __restrict__ bf,
    const float* __restrict__ wb, const float* __restrict__ bb,
    float* __restrict__ outf, float* __restrict__ outb)
{
    const int br  = blockIdx.y;
    const int idx = blockIdx.x * 256 + threadIdx.x;   // < MROWS*DI
    const int d = idx & (DI - 1);
    const int r = idx / DI;            // b*L + t (scan-time)
    const int t = r & (L_SEQ - 1);
    const int b = r / L_SEQ;

    const float* w  = br ? wb : wf;
    const float* bi = br ? bb : bf;
    float acc = bi[d];
#pragma unroll
    for (int k = 0; k < 4; k++) {
        const int tt = t - 3 + k;
        if (tt >= 0) {
            const int l = br ? (L_SEQ - 1 - tt) : tt;
            acc += xz[((size_t)(b * L_SEQ + l)) * (2 * DI) + d] * w[d * 4 + k];
        }
    }
    const float s = acc / (1.f + __expf(-acc));       // SiLU
    (br ? outb : outf)[idx] = s;
}

// ---------------- Selective scan + D skip + SiLU(z) gating, both branches ----------------
// Thread = (branch, b, d). 16 states in registers. B/C staged in smem, 16 steps/chunk.
// Output written at ORIGINAL sequence index l (backward branch un-flips on store).
__global__ __launch_bounds__(256) void scan_kernel(
    const float* __restrict__ xact_f, const float* __restrict__ xact_b,
    const float* __restrict__ dtr_f,  const float* __restrict__ dtr_b,
    const float* __restrict__ xdbl_f, const float* __restrict__ xdbl_b,
    const float* __restrict__ xz,
    const float* __restrict__ dtb_f,  const float* __restrict__ dtb_b,
    const float* __restrict__ alog_f, const float* __restrict__ alog_b,
    const float* __restrict__ dp_f,   const float* __restrict__ dp_b,
    float* __restrict__ y_f, float* __restrict__ y_b)
{
    const int br = blockIdx.z;
    const int b  = blockIdx.y;
    const int d  = blockIdx.x * 256 + threadIdx.x;

    const float* xact = br ? xact_b : xact_f;
    const float* dtr  = br ? dtr_b  : dtr_f;
    const float* xdbl = br ? xdbl_b : xdbl_f;
    const float* alog = br ? alog_b : alog_f;
    const float  dtbias = (br ? dtb_b : dtb_f)[d];
    const float  Dd     = (br ? dp_b  : dp_f)[d];
    float* yout = br ? y_b : y_f;

    float Av[DS];
#pragma unroll
    for (int n = 0; n < DS; n++) Av[n] = -__expf(alog[d * DS + n]);
    float h[DS];
#pragma unroll
    for (int n = 0; n < DS; n++) h[n] = 0.f;

    __shared__ float sBC[16][32];   // [step within chunk][B(16) | C(16)]

    for (int t0 = 0; t0 < L_SEQ; t0 += 16) {
        __syncthreads();
        for (int i = threadIdx.x; i < 16 * 32; i += 256) {
            const int ii = i >> 5, j = i & 31;
            sBC[ii][j] = xdbl[((size_t)(b * L_SEQ + t0 + ii)) * XDBL_W + DTR + j];
        }
        __syncthreads();
#pragma unroll 4
        for (int i = 0; i < 16; i++) {
            const int t = t0 + i;
            const size_t rowd = ((size_t)(b * L_SEQ + t)) * DI + d;
            const float x  = xact[rowd];
            const float dv = dtr[rowd] + dtbias;
            const float dt = (dv > 20.f) ? dv : log1pf(__expf(dv));   // softplus
            const float dtx = dt * x;
            float y = x * Dd;
#pragma unroll
            for (int n = 0; n < DS; n++) {
                const float dA = __expf(dt * Av[n]);
                h[n] = fmaf(dA, h[n], dtx * sBC[i][n]);
                y = fmaf(h[n], sBC[i][16 + n], y);
            }
            const int l = br ? (L_SEQ - 1 - t) : t;
            const float zv = xz[((size_t)(b * L_SEQ + l)) * (2 * DI) + DI + d];
            y *= zv / (1.f + __expf(-zv));                            // * SiLU(z)
            yout[((size_t)(b * L_SEQ + l)) * DI + d] = y;
        }
    }
}

// ---------------- Launch ----------------
extern "C" void kernel_launch(void* const* d_in, const int* in_sizes, int n_in,
                              void* d_out, int out_size)
{
    (void)in_sizes; (void)n_in; (void)out_size;
    const float* hs   = (const float*)d_in[0];
    const float* res  = (const float*)d_in[1];
    const float* pos  = (const float*)d_in[2];
    const float* nw   = (const float*)d_in[3];
    const float* nb   = (const float*)d_in[4];
    const float* inw  = (const float*)d_in[5];
    const float* outw = (const float*)d_in[6];
    const float* cw[2]   = {(const float*)d_in[7],  (const float*)d_in[14]};
    const float* cb[2]   = {(const float*)d_in[8],  (const float*)d_in[15]};
    const float* xpw[2]  = {(const float*)d_in[9],  (const float*)d_in[16]};
    const float* dtw[2]  = {(const float*)d_in[10], (const float*)d_in[17]};
    const float* dtpb[2] = {(const float*)d_in[11], (const float*)d_in[18]};
    const float* alog[2] = {(const float*)d_in[12], (const float*)d_in[19]};
    const float* Dp[2]   = {(const float*)d_in[13], (const float*)d_in[20]};

    float* out    = (float*)d_out;
    float* resout = out + (size_t)MROWS * DM;

    float *h, *xz, *xact, *xdbl, *dt, *y;
    cudaGetSymbolAddress((void**)&h,    g_h);
    cudaGetSymbolAddress((void**)&xz,   g_xz);
    cudaGetSymbolAddress((void**)&xact, g_xact);
    cudaGetSymbolAddress((void**)&xdbl, g_xdbl);
    cudaGetSymbolAddress((void**)&dt,   g_dt);
    cudaGetSymbolAddress((void**)&y,    g_y);

    float* xact_b = xact + (size_t)MROWS * DI;
    float* xdbl_b = xdbl + (size_t)MROWS * XDBL_W;
    float* dt_b   = dt   + (size_t)MROWS * DI;
    float* y_b    = y    + (size_t)MROWS * DI;

    // 1. residual add + LayerNorm + pos emb (also writes residual output)
    prenorm_kernel<<<MROWS, 256>>>(hs, res, pos, nw, nb, resout, h);

    // 2. in_proj: (16384 x 1024) @ (4096 x 1024)^T -> xz (16384 x 4096)
    sgemm_nt<<<dim3(2 * DI / 128, MROWS / 128), 256>>>(
        h, nullptr, DM, inw, DM, xz, 2 * DI, MROWS, 2 * DI, DM);

    // 3. depthwise causal conv + SiLU, both branches
    conv_silu_kernel<<<dim3(MROWS * DI / 256, 2), 256>>>(
        xz, cw[0], cb[0], cw[1], cb[1], xact, xact_b);

    // 4/5. per-branch x_proj (N=96) and dt GEMM (K=64)
    for (int br = 0; br < 2; br++) {
        float* xa = br ? xact_b : xact;
        float* xd = br ? xdbl_b : xdbl;
        float* dd = br ? dt_b   : dt;
        sgemm_nt<<<dim3(1, MROWS / 128), 256>>>(
            xa, nullptr, DI, xpw[br], DI, xd, XDBL_W, MROWS, XDBL_W, DI);
        sgemm_nt<<<dim3(DI / 128, MROWS / 128), 256>>>(
            xd, nullptr, XDBL_W, dtw[br], DTR, dd, DI, MROWS, DI, DTR);
    }

    // 6. selective scan + gating, both branches concurrently
    scan_kernel<<<dim3(DI / 256, B_SZ, 2), 256>>>(
        xact, xact_b, dt, dt_b, xdbl, xdbl_b, xz,
        dtpb[0], dtpb[1], alog[0], alog[1], Dp[0], Dp[1], y, y_b);

    // 7. out_proj on (y_f + y_b_unflipped), fused add inside GEMM A-loader
    sgemm_nt<<<dim3(DM / 128, MROWS / 128), 256>>>(
        y, y_b, DI, outw, DI, out, DM, MROWS, DM, DI);
}